// round 2
// baseline (speedup 1.0000x reference)
#include <cuda_runtime.h>

// 3-level db4 wavelet front-end, fully fused: one CTA per (b,c) row.
// Register-blocked (4 outputs/thread-chunk) with LDS.128/STS.128 everywhere;
// reflect boundary handling only on the 2-3 edge chunks per level.

#define NT 512
#define LEN0 8192
#define LEN1 4100   // analysis out of 8192
#define LEN2 2054   // analysis out of 4100
#define LEN3 1031   // analysis out of 2054
// padded strides (multiples of 4 floats -> 16B alignment of every buffer)
#define LEN1P 4100
#define LEN2P 2056
#define LEN3P 1032

__constant__ float c_dec_lo[8] = {
    -0.0105974018f, 0.0328830117f, 0.0308413818f, -0.1870348117f,
    -0.0279837694f, 0.6308807679f, 0.7148465706f, 0.2303778133f};
__constant__ float c_dec_hi[8] = {
    -0.2303778133f, 0.7148465706f, -0.6308807679f, -0.0279837694f,
     0.1870348117f, 0.0308413818f, -0.0328830117f, -0.0105974018f};

// Synthesis polyphase taps (transpose conv, crop 7, T = 2L-8):
//   out[2u]   = e0*a[u]   + e1*a[u+1] + e2*a[u+2] + e3*a[u+3]
//   out[2u+1] = o0*a[u+1] + o1*a[u+2] + o2*a[u+3] + o3*a[u+4]
__constant__ float c_lo_e[4] = {-0.0105974018f, 0.0308413818f, -0.0279837694f, 0.7148465706f};
__constant__ float c_lo_o[4] = { 0.0328830117f, -0.1870348117f, 0.6308807679f, 0.2303778133f};
__constant__ float c_hi_e[4] = {-0.2303778133f, -0.6308807679f, 0.1870348117f, -0.0328830117f};
__constant__ float c_hi_o[4] = { 0.7148465706f, -0.0279837694f, 0.0308413818f, -0.0105974018f};

// ---------------- analysis: stride-2 correlation, reflect pad 7 ----------------
__device__ __forceinline__ void analysis_step(const float* __restrict__ in, int L,
                                              float* __restrict__ lo, float* __restrict__ hi,
                                              int Lout, int tid) {
    const int nchunk = (Lout + 3) >> 2;
    const int jhi = (L - 8) >> 3;        // last j with 8j+7 <= L-1
    const int twoLm2 = 2 * L - 2;
    for (int j = tid; j < nchunk; j += NT) {
        if (j >= 1 && j <= jhi) {
            // interior: inputs [8j-7, 8j+6] subset of v[0..15] loaded from 8j-8
            const float4* in4 = reinterpret_cast<const float4*>(in) + (2 * j - 2);
            float v[16];
#pragma unroll
            for (int q = 0; q < 4; q++) {
                float4 t = in4[q];
                v[4 * q] = t.x; v[4 * q + 1] = t.y; v[4 * q + 2] = t.z; v[4 * q + 3] = t.w;
            }
            float slo[4], shi[4];
#pragma unroll
            for (int m = 0; m < 4; m++) {
                float sl = 0.f, sh = 0.f;
#pragma unroll
                for (int k = 0; k < 8; k++) {
                    float xv = v[2 * m + 1 + k];
                    sl = fmaf(xv, c_dec_lo[k], sl);
                    sh = fmaf(xv, c_dec_hi[k], sh);
                }
                slo[m] = sl; shi[m] = sh;
            }
            *reinterpret_cast<float4*>(lo + 4 * j) = make_float4(slo[0], slo[1], slo[2], slo[3]);
            *reinterpret_cast<float4*>(hi + 4 * j) = make_float4(shi[0], shi[1], shi[2], shi[3]);
        } else {
            // boundary chunk: scalar with reflect, also handles Lout tail
#pragma unroll
            for (int m = 0; m < 4; m++) {
                int o = 4 * j + m;
                if (o >= Lout) break;
                int base = 2 * o - 7;
                float sl = 0.f, sh = 0.f;
#pragma unroll
                for (int k = 0; k < 8; k++) {
                    int i = base + k;
                    i = i < 0 ? -i : i;
                    i = min(i, twoLm2 - i);
                    float xv = in[i];
                    sl = fmaf(xv, c_dec_lo[k], sl);
                    sh = fmaf(xv, c_dec_hi[k], sh);
                }
                lo[o] = sl;
                hi[o] = sh;
            }
        }
    }
}

// ---------------- synthesis: polyphase transpose conv, no boundary cases --------
// chunk of 4 u's: reads a[4j..4j+7] (2x LDS.128), writes out[8j..8j+7] (2x ST.128)
template <bool TO_GMEM>
__device__ __forceinline__ void synth_step(const float* __restrict__ a, int L,
                                           const float* __restrict__ wE, const float* __restrict__ wO,
                                           float* __restrict__ out, int tid) {
    const int halfT = L - 4;
    const int nchunk = (halfT + 3) >> 2;
    const float e0 = wE[0], e1 = wE[1], e2 = wE[2], e3 = wE[3];
    const float o0 = wO[0], o1 = wO[1], o2 = wO[2], o3 = wO[3];
    for (int j = tid; j < nchunk; j += NT) {
        const int u0 = 4 * j;
        if (u0 + 4 <= halfT) {
            const float4* a4 = reinterpret_cast<const float4*>(a + u0);
            float4 A = a4[0], B = a4[1];
            float v[8] = {A.x, A.y, A.z, A.w, B.x, B.y, B.z, B.w};
            float r[8];
#pragma unroll
            for (int m = 0; m < 4; m++) {
                r[2 * m]     = fmaf(e0, v[m],     fmaf(e1, v[m + 1], fmaf(e2, v[m + 2], e3 * v[m + 3])));
                r[2 * m + 1] = fmaf(o0, v[m + 1], fmaf(o1, v[m + 2], fmaf(o2, v[m + 3], o3 * v[m + 4])));
            }
            float4* o4 = reinterpret_cast<float4*>(out + 8 * j);
            o4[0] = make_float4(r[0], r[1], r[2], r[3]);
            o4[1] = make_float4(r[4], r[5], r[6], r[7]);
        } else {
            for (int u = u0; u < halfT; u++) {
                float a0 = a[u], a1 = a[u + 1], a2 = a[u + 2], a3 = a[u + 3], a4v = a[u + 4];
                out[2 * u]     = fmaf(e0, a0, fmaf(e1, a1, fmaf(e2, a2, e3 * a3)));
                out[2 * u + 1] = fmaf(o0, a1, fmaf(o1, a2, fmaf(o2, a3, o3 * a4v)));
            }
        }
    }
}

__global__ void __launch_bounds__(NT, 2)
dwt_frontend_kernel(const float* __restrict__ x, float* __restrict__ out) {
    extern __shared__ float s[];
    float* X  = s;               // 8192
    float* D1 = X  + LEN0;
    float* A1 = D1 + LEN1P;      // also recon scratch (4100)
    float* D2 = A1 + LEN1P;
    float* A2 = D2 + LEN2P;      // also recon scratch (2054)
    float* D3 = A2 + LEN2P;
    float* A3 = D3 + LEN3P;

    const int tid = threadIdx.x;
    const int row = blockIdx.x;
    const float* xg = x + (size_t)row * LEN0;

    {
        const float4* xg4 = reinterpret_cast<const float4*>(xg);
        float4* X4 = reinterpret_cast<float4*>(X);
        for (int i = tid; i < LEN0 / 4; i += NT) X4[i] = xg4[i];
    }
    __syncthreads();

    analysis_step(X,  LEN0, A1, D1, LEN1, tid);
    __syncthreads();
    analysis_step(A1, LEN1, A2, D2, LEN2, tid);
    __syncthreads();
    analysis_step(A2, LEN2, A3, D3, LEN3, tid);
    __syncthreads();

    const size_t bstride = (size_t)gridDim.x * LEN0;
    float* ob = out + (size_t)row * LEN0;

    // Band 3: REC_HI(D1) -> 8192 -> gmem
    synth_step<true>(D1, LEN1, c_hi_e, c_hi_o, ob + 3 * bstride, tid);
    // Band 2: REC_HI(D2) -> A1 (4100), then REC_LO -> gmem
    synth_step<false>(D2, LEN2, c_hi_e, c_hi_o, A1, tid);
    __syncthreads();
    synth_step<true>(A1, LEN1, c_lo_e, c_lo_o, ob + 2 * bstride, tid);
    // Band 1: REC_HI(D3) -> A2 (2054), REC_LO -> A1 (4100), REC_LO -> gmem
    synth_step<false>(D3, LEN3, c_hi_e, c_hi_o, A2, tid);
    __syncthreads();
    synth_step<false>(A2, LEN2, c_lo_e, c_lo_o, A1, tid);
    __syncthreads();
    synth_step<true>(A1, LEN1, c_lo_e, c_lo_o, ob + 1 * bstride, tid);
    // Band 0: REC_LO(A3) -> A2, REC_LO -> A1, REC_LO -> gmem
    synth_step<false>(A3, LEN3, c_lo_e, c_lo_o, A2, tid);
    __syncthreads();
    synth_step<false>(A2, LEN2, c_lo_e, c_lo_o, A1, tid);
    __syncthreads();
    synth_step<true>(A1, LEN1, c_lo_e, c_lo_o, ob, tid);
}

extern "C" void kernel_launch(void* const* d_in, const int* in_sizes, int n_in,
                              void* d_out, int out_size) {
    const float* x = (const float*)d_in[0];
    float* out = (float*)d_out;
    const size_t smem = (size_t)(LEN0 + 2 * LEN1P + 2 * LEN2P + 2 * LEN3P) * sizeof(float); // 90304 B
    cudaFuncSetAttribute(dwt_frontend_kernel,
                         cudaFuncAttributeMaxDynamicSharedMemorySize, (int)smem);
    dwt_frontend_kernel<<<2048, NT, smem>>>(x, out);
}

// round 5
// speedup vs baseline: 1.1400x; 1.1400x over previous
#include <cuda_runtime.h>

// 3-level db4 wavelet front-end, fully fused: one CTA per (b,c) row.
// R4: phase-fused synthesis (7 barriers) + corrected smem arena aliasing.
// Invariant: within each barrier-delimited phase, the set of smem regions
// written is disjoint from the set of smem regions read (no intra-phase sync).

#define NT 512
#define LEN0 8192
#define LEN1 4100
#define LEN2 2054
#define LEN3 1031

// ---- smem arena (floats); all offsets 16B-aligned ----
// L1 : read X[0,8192)            write A1[8192,12292) D1[12292,16392)
// L2 : read A1                   write A2[0,2056)     D2[2056,4112)
// L3 : read A2                   write D3[4112,5144)  A3[5144,6176)
// P1 : read D1,D2,D3,A3          write B0_1[0,2056)   B2_1[6176,10276) B1_1[16392,18448)
// P2 : read B2_1,B1_1,B0_1       write B0_2[2056,6156) B1_2[10276,14376)
// P3 : read B1_2,B0_2            write gmem only
#define ARENA    18448
#define OFF_X    0
#define OFF_A1   8192
#define OFF_D1   12292
#define OFF_A2   0
#define OFF_D2   2056
#define OFF_D3   4112
#define OFF_A3   5144
#define OFF_B0_1 0
#define OFF_B2_1 6176
#define OFF_B1_1 16392
#define OFF_B0_2 2056
#define OFF_B1_2 10276

__constant__ float c_dec_lo[8] = {
    -0.0105974018f, 0.0328830117f, 0.0308413818f, -0.1870348117f,
    -0.0279837694f, 0.6308807679f, 0.7148465706f, 0.2303778133f};
__constant__ float c_dec_hi[8] = {
    -0.2303778133f, 0.7148465706f, -0.6308807679f, -0.0279837694f,
     0.1870348117f, 0.0308413818f, -0.0328830117f, -0.0105974018f};

// Synthesis polyphase taps (transpose conv, crop 7, T = 2L-8):
//   out[2u]   = e0*a[u]   + e1*a[u+1] + e2*a[u+2] + e3*a[u+3]
//   out[2u+1] = o0*a[u+1] + o1*a[u+2] + o2*a[u+3] + o3*a[u+4]
__constant__ float c_lo_e[4] = {-0.0105974018f, 0.0308413818f, -0.0279837694f, 0.7148465706f};
__constant__ float c_lo_o[4] = { 0.0328830117f, -0.1870348117f, 0.6308807679f, 0.2303778133f};
__constant__ float c_hi_e[4] = {-0.2303778133f, -0.6308807679f, 0.1870348117f, -0.0328830117f};
__constant__ float c_hi_o[4] = { 0.7148465706f, -0.0279837694f, 0.0308413818f, -0.0105974018f};

// ---------------- analysis: stride-2 correlation, reflect pad 7 ----------------
__device__ __forceinline__ void analysis_step(const float* __restrict__ in, int L,
                                              float* __restrict__ lo, float* __restrict__ hi,
                                              int Lout, int tid) {
    const int nchunk = (Lout + 3) >> 2;
    const int jhi = (L - 8) >> 3;
    const int twoLm2 = 2 * L - 2;
    for (int j = tid; j < nchunk; j += NT) {
        if (j >= 1 && j <= jhi) {
            const float4* in4 = reinterpret_cast<const float4*>(in) + (2 * j - 2);
            float v[16];
#pragma unroll
            for (int q = 0; q < 4; q++) {
                float4 t = in4[q];
                v[4 * q] = t.x; v[4 * q + 1] = t.y; v[4 * q + 2] = t.z; v[4 * q + 3] = t.w;
            }
            float slo[4], shi[4];
#pragma unroll
            for (int m = 0; m < 4; m++) {
                float sl = 0.f, sh = 0.f;
#pragma unroll
                for (int k = 0; k < 8; k++) {
                    float xv = v[2 * m + 1 + k];
                    sl = fmaf(xv, c_dec_lo[k], sl);
                    sh = fmaf(xv, c_dec_hi[k], sh);
                }
                slo[m] = sl; shi[m] = sh;
            }
            *reinterpret_cast<float4*>(lo + 4 * j) = make_float4(slo[0], slo[1], slo[2], slo[3]);
            *reinterpret_cast<float4*>(hi + 4 * j) = make_float4(shi[0], shi[1], shi[2], shi[3]);
        } else {
#pragma unroll
            for (int m = 0; m < 4; m++) {
                int o = 4 * j + m;
                if (o >= Lout) break;
                int base = 2 * o - 7;
                float sl = 0.f, sh = 0.f;
#pragma unroll
                for (int k = 0; k < 8; k++) {
                    int i = base + k;
                    i = i < 0 ? -i : i;
                    i = min(i, twoLm2 - i);
                    float xv = in[i];
                    sl = fmaf(xv, c_dec_lo[k], sl);
                    sh = fmaf(xv, c_dec_hi[k], sh);
                }
                lo[o] = sl;
                hi[o] = sh;
            }
        }
    }
}

// ---------------- synthesis: polyphase transpose conv, no boundary cases --------
__device__ __forceinline__ void synth_step(const float* __restrict__ a, int L,
                                           const float* __restrict__ wE, const float* __restrict__ wO,
                                           float* __restrict__ out, int tid) {
    const int halfT = L - 4;
    const int nchunk = (halfT + 3) >> 2;
    const float e0 = wE[0], e1 = wE[1], e2 = wE[2], e3 = wE[3];
    const float o0 = wO[0], o1 = wO[1], o2 = wO[2], o3 = wO[3];
    for (int j = tid; j < nchunk; j += NT) {
        const int u0 = 4 * j;
        if (u0 + 4 <= halfT) {
            const float4* a4 = reinterpret_cast<const float4*>(a + u0);
            float4 A = a4[0], B = a4[1];
            float v[8] = {A.x, A.y, A.z, A.w, B.x, B.y, B.z, B.w};
            float r[8];
#pragma unroll
            for (int m = 0; m < 4; m++) {
                r[2 * m]     = fmaf(e0, v[m],     fmaf(e1, v[m + 1], fmaf(e2, v[m + 2], e3 * v[m + 3])));
                r[2 * m + 1] = fmaf(o0, v[m + 1], fmaf(o1, v[m + 2], fmaf(o2, v[m + 3], o3 * v[m + 4])));
            }
            float4* o4 = reinterpret_cast<float4*>(out + 8 * j);
            o4[0] = make_float4(r[0], r[1], r[2], r[3]);
            o4[1] = make_float4(r[4], r[5], r[6], r[7]);
        } else {
            for (int u = u0; u < halfT; u++) {
                float a0 = a[u], a1 = a[u + 1], a2 = a[u + 2], a3 = a[u + 3], a4v = a[u + 4];
                out[2 * u]     = fmaf(e0, a0, fmaf(e1, a1, fmaf(e2, a2, e3 * a3)));
                out[2 * u + 1] = fmaf(o0, a1, fmaf(o1, a2, fmaf(o2, a3, o3 * a4v)));
            }
        }
    }
}

__global__ void __launch_bounds__(NT, 3)
dwt_frontend_kernel(const float* __restrict__ x, float* __restrict__ out) {
    extern __shared__ float s[];
    const int tid = threadIdx.x;
    const int row = blockIdx.x;
    const float* xg = x + (size_t)row * LEN0;

    // ---- load row (float4) ----
    {
        const float4* xg4 = reinterpret_cast<const float4*>(xg);
        float4* X4 = reinterpret_cast<float4*>(s + OFF_X);
        for (int i = tid; i < LEN0 / 4; i += NT) X4[i] = xg4[i];
    }
    __syncthreads();

    // ---- analysis cascade ----
    analysis_step(s + OFF_X,  LEN0, s + OFF_A1, s + OFF_D1, LEN1, tid);
    __syncthreads();
    analysis_step(s + OFF_A1, LEN1, s + OFF_A2, s + OFF_D2, LEN2, tid);
    __syncthreads();
    analysis_step(s + OFF_A2, LEN2, s + OFF_A3, s + OFF_D3, LEN3, tid);
    __syncthreads();

    const size_t bstride = (size_t)gridDim.x * LEN0;
    float* ob = out + (size_t)row * LEN0;

    // ---- P1: all depth-1 synthesis stages (reads D1,D2,D3,A3) ----
    synth_step(s + OFF_D1, LEN1, c_hi_e, c_hi_o, ob + 3 * bstride, tid);  // band3 -> gmem
    synth_step(s + OFF_D2, LEN2, c_hi_e, c_hi_o, s + OFF_B2_1, tid);      // -> [6176,10276)
    synth_step(s + OFF_D3, LEN3, c_hi_e, c_hi_o, s + OFF_B1_1, tid);      // -> [16392,18448)
    synth_step(s + OFF_A3, LEN3, c_lo_e, c_lo_o, s + OFF_B0_1, tid);      // -> [0,2056)
    __syncthreads();

    // ---- P2: depth-2 stages (reads B2_1,B1_1,B0_1) ----
    synth_step(s + OFF_B2_1, LEN1, c_lo_e, c_lo_o, ob + 2 * bstride, tid); // band2 -> gmem
    synth_step(s + OFF_B1_1, LEN2, c_lo_e, c_lo_o, s + OFF_B1_2, tid);     // -> [10276,14376)
    synth_step(s + OFF_B0_1, LEN2, c_lo_e, c_lo_o, s + OFF_B0_2, tid);     // -> [2056,6156)
    __syncthreads();

    // ---- P3: depth-3 stages -> gmem ----
    synth_step(s + OFF_B1_2, LEN1, c_lo_e, c_lo_o, ob + 1 * bstride, tid); // band1 -> gmem
    synth_step(s + OFF_B0_2, LEN1, c_lo_e, c_lo_o, ob, tid);               // band0 -> gmem
}

extern "C" void kernel_launch(void* const* d_in, const int* in_sizes, int n_in,
                              void* d_out, int out_size) {
    const float* x = (const float*)d_in[0];
    float* out = (float*)d_out;
    const size_t smem = (size_t)ARENA * sizeof(float);   // 73792 B -> 3 CTAs/SM
    cudaFuncSetAttribute(dwt_frontend_kernel,
                         cudaFuncAttributeMaxDynamicSharedMemorySize, (int)smem);
    dwt_frontend_kernel<<<2048, NT, smem>>>(x, out);
}